// round 14
// baseline (speedup 1.0000x reference)
#include <cuda_runtime.h>
#include <math.h>

#define NC     124
#define CPAD   128
#define CH     64
#define IN_HW  120
#define OUT_HW 480
#define NPIX   (OUT_HW * OUT_HW)   // 230400
#define NTAP   (IN_HW * IN_HW)     // 14400
#define EPSV   1e-8f
#define NOUTB  600                  // k_out blocks (24 taps each)
#define K1B    720                  // gramG blocks: 120 gram + 600 G
#define ZCHUNK 640                  // f4s of g_C zeroed per K1 block (720*640*4 = NTAP*CPAD)

// ---------------- static device scratch ----------------
__device__ int   g_iszero[NC];
__device__ __align__(16) float g_gram[NTAP * 8];       // S,H,V,D,AD per tap
__device__ __align__(16) float g_G[NTAP * CPAD];       // f_t . mn_c
__device__ __align__(16) float g_C[NTAP * CPAD];       // selected coefficient
__device__ __align__(16) float4 g_part4[NOUTB * 2048]; // k_out partials (19.7MB)
__device__ float g_den[CPAD];
__device__ float g_cnt[CPAD];

// =============== K1: zero g_C + gram rows (0..119) + G table (120..719) =======
__global__ __launch_bounds__(512) void k_gramG(const float* __restrict__ feats,
                                               const float* __restrict__ memory) {
    __shared__ __align__(16) float sbuf[7680];   // 30.7KB (union of branches)
    const int tid = threadIdx.x;

    // distributed zeroing of g_C (consumed by phaseA, next kernel)
    {
        const int base = blockIdx.x * ZCHUNK;
        const float4 z = make_float4(0.f, 0.f, 0.f, 0.f);
#pragma unroll
        for (int l = tid; l < ZCHUNK; l += 512)
            ((float4*)g_C)[base + l] = z;
    }

    if (blockIdx.x < 120) {
        // ---- gram row-block: y = bid, thread x computes 5 dot-sums over ch ----
        float* bufA = sbuf;            // 32ch x 120
        float* bufB = sbuf + 3840;     // 32ch x 120 (row y+1)
        const int y  = blockIdx.x;
        const int yp = min(y + 1, IN_HW - 1);
        const int x  = tid;
        const int xp = min(x + 1, IN_HW - 1);
        float s = 0.f, h = 0.f, vv = 0.f, dd = 0.f, ad = 0.f;

#pragma unroll
        for (int pass = 0; pass < 2; pass++) {
            __syncthreads();
#pragma unroll
            for (int l = tid; l < 3840; l += 512) {
                const int ch = l / 120, xx = l - ch * 120;
                const int cg = pass * 32 + ch;
                bufA[l] = feats[cg * NTAP + y  * IN_HW + xx];
                bufB[l] = feats[cg * NTAP + yp * IN_HW + xx];
            }
            __syncthreads();
            if (x < IN_HW) {
#pragma unroll 8
                for (int ch = 0; ch < 32; ch++) {
                    const float a = bufA[ch * 120 + x];
                    const float b = bufA[ch * 120 + xp];
                    const float c = bufB[ch * 120 + x];
                    const float d = bufB[ch * 120 + xp];
                    s  = fmaf(a, a, s);
                    h  = fmaf(a, b, h);
                    vv = fmaf(a, c, vv);
                    dd = fmaf(a, d, dd);
                    ad = fmaf(b, c, ad);
                }
            }
        }
        if (x < IN_HW) {
            float* o = &g_gram[(y * IN_HW + x) * 8];
            o[0] = s; o[1] = h; o[2] = vv; o[3] = dd; o[4] = ad;
        }
        if (blockIdx.x == 0) {
            if (tid < CPAD) { g_den[tid] = 0.f; g_cnt[tid] = 0.f; }
            if (tid < NC) {
                int isz = 1;
#pragma unroll
                for (int k = 0; k < 16; k++) {
                    float4 v = ((const float4*)memory)[tid * 16 + k];
                    isz &= (v.x == 0.f) & (v.y == 0.f) & (v.z == 0.f) & (v.w == 0.f);
                }
                g_iszero[tid] = isz;
            }
        }
    } else {
        // ---- G table: 24 taps, in-smem transpose from raw feats, (c,q) layout ----
        float* fsm = sbuf;                         // 24 taps x 64 ch
        const int t0 = (blockIdx.x - 120) * 24;
        const int c = tid >> 2, q = tid & 3;
        const bool valid = c < NC;
        float4 mq[4];
        float n2p = 0.f;
#pragma unroll
        for (int j = 0; j < 4; j++) {
            float4 v = valid ? ((const float4*)memory)[c * 16 + q * 4 + j]
                             : make_float4(0.f, 0.f, 0.f, 0.f);
            n2p += v.x * v.x + v.y * v.y + v.z * v.z + v.w * v.w;
            mq[j] = v;
        }
        n2p += __shfl_xor_sync(0xffffffffu, n2p, 1);
        n2p += __shfl_xor_sync(0xffffffffu, n2p, 2);
        const float inv = 1.0f / fmaxf(sqrtf(n2p), EPSV);
#pragma unroll
        for (int j = 0; j < 4; j++) {
            mq[j].x *= inv; mq[j].y *= inv; mq[j].z *= inv; mq[j].w *= inv;
        }
        // transpose-load: fsm[tt*64 + ch] = feats[ch][t0+tt]
#pragma unroll
        for (int k = 0; k < 3; k++) {
            const int l = k * 512 + tid;           // < 1536
            const int ch = l / 24, tt = l - ch * 24;
            fsm[tt * CH + ch] = feats[ch * NTAP + t0 + tt];
        }
        __syncthreads();
#pragma unroll 4
        for (int tt = 0; tt < 24; tt++) {
            const float4* fr = (const float4*)(fsm + tt * CH + q * 16);
            float a0 = 0.f, a1 = 0.f, a2 = 0.f, a3 = 0.f;
#pragma unroll
            for (int j = 0; j < 4; j++) {
                float4 f = fr[j];
                a0 = fmaf(f.x, mq[j].x, a0);
                a1 = fmaf(f.y, mq[j].y, a1);
                a2 = fmaf(f.z, mq[j].z, a2);
                a3 = fmaf(f.w, mq[j].w, a3);
            }
            float d = (a0 + a1) + (a2 + a3);
            d += __shfl_xor_sync(0xffffffffu, d, 1);
            d += __shfl_xor_sync(0xffffffffu, d, 2);
            if (q == 0 && valid) g_G[(t0 + tt) * CPAD + c] = d;
        }
    }
}

// ---------------- per-pixel geometry helper ----------------
struct Geo { int t00, t01, t10, t11; float w00, w01, w10, w11; };
__device__ __forceinline__ Geo pix_geo(int i) {
    const int oy = i / OUT_HW, ox = i - oy * OUT_HW;
    const float fy = 0.25f * (float)oy - 0.375f;
    const float fx = 0.25f * (float)ox - 0.375f;
    const int by = (int)floorf(fy), bx = (int)floorf(fx);
    int y0, x0; float u, v;
    if (by < 0)               { y0 = 0;         u = 0.f; }
    else if (by >= IN_HW - 1) { y0 = IN_HW - 1; u = 0.f; }
    else                      { y0 = by;        u = fy - (float)by; }
    if (bx < 0)               { x0 = 0;         v = 0.f; }
    else if (bx >= IN_HW - 1) { x0 = IN_HW - 1; v = 0.f; }
    else                      { x0 = bx;        v = fx - (float)bx; }
    const int yp = min(y0 + 1, IN_HW - 1), xp = min(x0 + 1, IN_HW - 1);
    const float wu0 = 1.f - u, wv0 = 1.f - v;
    Geo g;
    g.w00 = wu0 * wv0; g.w01 = wu0 * v; g.w10 = u * wv0; g.w11 = u * v;
    g.t00 = y0 * IN_HW + x0; g.t01 = y0 * IN_HW + xp;
    g.t10 = yp * IN_HW + x0; g.t11 = yp * IN_HW + xp;
    return g;
}

__device__ __forceinline__ float pix_sim(const Geo& g, int c) {
    const float dot = g.w00 * g_G[g.t00 * CPAD + c] + g.w01 * g_G[g.t01 * CPAD + c]
                    + g.w10 * g_G[g.t10 * CPAD + c] + g.w11 * g_G[g.t11 * CPAD + c];
    const float4 q00 = *(const float4*)&g_gram[g.t00 * 8];
    const float ad00 = g_gram[g.t00 * 8 + 4];
    const float4 q01 = *(const float4*)&g_gram[g.t01 * 8];
    const float4 q10 = *(const float4*)&g_gram[g.t10 * 8];
    const float S11  = g_gram[g.t11 * 8];
    float n2 = g.w00 * g.w00 * q00.x + g.w01 * g.w01 * q01.x
             + g.w10 * g.w10 * q10.x + g.w11 * g.w11 * S11
             + 2.f * (g.w00 * g.w01 * q00.y + g.w10 * g.w11 * q10.y
                    + g.w00 * g.w10 * q00.z + g.w01 * g.w11 * q01.z
                    + g.w00 * g.w11 * q00.w + g.w01 * g.w10 * ad00);
    n2 = fmaxf(n2, 0.f);
    return 1.f - dot / fmaxf(sqrtf(n2), EPSV);
}

// =============== K2: per-pixel weights + coefficient scatter (2 px/thread) ====
__global__ __launch_bounds__(512) void k_phaseA(const int* __restrict__ seg) {
    __shared__ float s_den[CPAD], s_cnt[CPAD];
    __shared__ int   s_isz[CPAD];
    const int tid = threadIdx.x;
    if (tid < CPAD) {
        s_den[tid] = 0.f; s_cnt[tid] = 0.f;
        s_isz[tid] = (tid < NC) ? g_iszero[tid] : 0;
    }
    __syncthreads();

    const int iA = blockIdx.x * 512 + tid;        // grid 225: iA < 115200
    const int iB = iA + NPIX / 2;
    const int cA = seg[iA];
    const int cB = seg[iB];
    const Geo ga = pix_geo(iA);
    const Geo gb = pix_geo(iB);

    const float sA = pix_sim(ga, cA);
    const float sB = pix_sim(gb, cB);

    const float cmA = s_isz[cA] ? 1.0f : sA;
    const float cmB = s_isz[cB] ? 1.0f : sB;

    atomicAdd(&g_C[ga.t00 * CPAD + cA], cmA * ga.w00);
    atomicAdd(&g_C[ga.t01 * CPAD + cA], cmA * ga.w01);
    atomicAdd(&g_C[ga.t10 * CPAD + cA], cmA * ga.w10);
    atomicAdd(&g_C[ga.t11 * CPAD + cA], cmA * ga.w11);
    atomicAdd(&g_C[gb.t00 * CPAD + cB], cmB * gb.w00);
    atomicAdd(&g_C[gb.t01 * CPAD + cB], cmB * gb.w01);
    atomicAdd(&g_C[gb.t10 * CPAD + cB], cmB * gb.w10);
    atomicAdd(&g_C[gb.t11 * CPAD + cB], cmB * gb.w11);
    atomicAdd(&s_den[cA], cmA);
    atomicAdd(&s_cnt[cA], 1.0f);
    atomicAdd(&s_den[cB], cmB);
    atomicAdd(&s_cnt[cB], 1.0f);

    __syncthreads();
    if (tid < NC) {
        atomicAdd(&g_den[tid], s_den[tid]);
        atomicAdd(&g_cnt[tid], s_cnt[tid]);
    }
}

// =============== K3: output GEMM partials (in-smem transpose, no atomics) =====
// thread (c = tid>>1, h = tid&1); acc[j] covers channels 8j+4h .. 8j+4h+3
__global__ __launch_bounds__(256) void k_out(const float* __restrict__ feats) {
    __shared__ __align__(16) float fsm[24 * CH];     // 6 KB
    __shared__ __align__(16) float csm[24 * CPAD];   // 12 KB
    const int tid = threadIdx.x;
    const int c = tid >> 1, h = tid & 1;
    const int t0 = blockIdx.x * 24;                  // 600 * 24 = 14400

    // transpose-load feats tile: fsm[tt*64 + ch] = feats[ch][t0+tt]
#pragma unroll
    for (int k = 0; k < 6; k++) {
        const int l = k * 256 + tid;                 // < 1536
        const int ch = l / 24, tt = l - ch * 24;
        fsm[tt * CH + ch] = feats[ch * NTAP + t0 + tt];
    }
#pragma unroll
    for (int k = 0; k < 3; k++)
        ((float4*)csm)[tid + k * 256] = ((const float4*)(g_C + t0 * CPAD))[tid + k * 256];
    __syncthreads();

    float4 acc[8];
#pragma unroll
    for (int j = 0; j < 8; j++) acc[j] = make_float4(0.f, 0.f, 0.f, 0.f);

#pragma unroll 4
    for (int tt = 0; tt < 24; tt++) {
        const float coef = csm[tt * CPAD + c];
        const float4* fr = (const float4*)fsm + tt * 16 + h;
#pragma unroll
        for (int j = 0; j < 8; j++) {
            const float4 f = fr[2 * j];
            acc[j].x = fmaf(coef, f.x, acc[j].x);
            acc[j].y = fmaf(coef, f.y, acc[j].y);
            acc[j].z = fmaf(coef, f.z, acc[j].z);
            acc[j].w = fmaf(coef, f.w, acc[j].w);
        }
    }
    // coalesced partial store: g_part4[(b*8+j)*256 + tid]
#pragma unroll
    for (int j = 0; j < 8; j++)
        g_part4[(blockIdx.x * 8 + j) * 256 + tid] = acc[j];
}

// =============== K4: reduce partials + final blend ============================
__global__ __launch_bounds__(256) void k_blend(const float* __restrict__ memory,
                                               float* __restrict__ out) {
    __shared__ float red[256];
    const int c  = blockIdx.x;                 // 0..123
    const int ch = threadIdx.x & 63;
    const int w  = threadIdx.x >> 6;           // 0..3 split over partial blocks
    const int j  = ch >> 3, h = (ch >> 2) & 1, k = ch & 3;
    const float* P = (const float*)g_part4;
    const int base = (j * 256 + 2 * c + h) * 4 + k;   // + b*8192

    float sum = 0.f;
#pragma unroll 6
    for (int b = w; b < NOUTB; b += 4)
        sum += P[base + b * 8192];
    red[threadIdx.x] = sum;
    __syncthreads();

    if (w == 0) {
        const float accv = red[ch] + red[ch + 64] + red[ch + 128] + red[ch + 192];
        const float mem = memory[c * CH + ch];
        const float cnt = g_cnt[c];
        float o;
        if (cnt < 0.5f) {
            o = mem;                                     // class absent
        } else if (g_iszero[c]) {
            o = accv / fmaxf(g_den[c], 1.0f);            // class mean (den==cnt)
        } else {
            const float dv = g_den[c];
            const float denom = (dv != 0.0f) ? dv : 1.0f;
            o = 0.9f * mem + 0.1f * (accv / denom);      // momentum update
        }
        out[c * CH + ch] = o;
    }
}

// ---------------- launch ----------------
extern "C" void kernel_launch(void* const* d_in, const int* in_sizes, int n_in,
                              void* d_out, int out_size) {
    const float* feats  = (const float*)d_in[0];   // (1,64,120,120)
    const float* memory = (const float*)d_in[1];   // (124,1,64)
    const int*   seg    = (const int*)d_in[2];     // (1,480,480)
    float* out = (float*)d_out;                    // (124,1,64)

    k_gramG<<<K1B, 512>>>(feats, memory);
    k_phaseA<<<225, 512>>>(seg);
    k_out<<<NOUTB, 256>>>(feats);
    k_blend<<<NC, 256>>>(memory, out);
}

// round 15
// speedup vs baseline: 1.0379x; 1.0379x over previous
#include <cuda_runtime.h>
#include <math.h>

#define NC     124
#define CPAD   128
#define CH     64
#define IN_HW  120
#define OUT_HW 480
#define NPIX   (OUT_HW * OUT_HW)   // 230400
#define NTAP   (IN_HW * IN_HW)     // 14400
#define EPSV   1e-8f
#define NOUTB  600                  // k_out blocks (24 taps each)
#define K1B    720                  // gramG blocks: 120 gram + 600 G
#define ZCHUNK 640                  // f4s of g_C zeroed per K1 block (720*640*4 = NTAP*CPAD)

// ---------------- static device scratch ----------------
__device__ int   g_iszero[NC];
__device__ __align__(16) float g_gram[NTAP * 8];       // S,H,V,D,AD per tap
__device__ __align__(16) float g_G[NTAP * CPAD];       // f_t . mn_c
__device__ __align__(16) float g_C[NTAP * CPAD];       // selected coefficient
__device__ __align__(16) float4 g_part4[NOUTB * 2048]; // k_out partials (19.7MB)
__device__ float g_den[CPAD];
__device__ float g_cnt[CPAD];

// =============== K1: zero g_C + gram rows (0..119) + G table (120..719) =======
__global__ __launch_bounds__(512) void k_gramG(const float* __restrict__ feats,
                                               const float* __restrict__ memory) {
    __shared__ __align__(16) float sbuf[7680];   // 30.7KB (union of branches)
    const int tid = threadIdx.x;

    // distributed zeroing of g_C (consumed by phaseA, next kernel)
    {
        const int base = blockIdx.x * ZCHUNK;
        const float4 z = make_float4(0.f, 0.f, 0.f, 0.f);
#pragma unroll
        for (int l = tid; l < ZCHUNK; l += 512)
            ((float4*)g_C)[base + l] = z;
    }

    if (blockIdx.x < 120) {
        // ---- gram row-block: y = bid, thread x computes 5 dot-sums over ch ----
        float* bufA = sbuf;            // 32ch x 120
        float* bufB = sbuf + 3840;     // 32ch x 120 (row y+1)
        const int y  = blockIdx.x;
        const int yp = min(y + 1, IN_HW - 1);
        const int x  = tid;
        const int xp = min(x + 1, IN_HW - 1);
        float s = 0.f, h = 0.f, vv = 0.f, dd = 0.f, ad = 0.f;

#pragma unroll
        for (int pass = 0; pass < 2; pass++) {
            __syncthreads();
#pragma unroll
            for (int l = tid; l < 3840; l += 512) {
                const int ch = l / 120, xx = l - ch * 120;
                const int cg = pass * 32 + ch;
                bufA[l] = feats[cg * NTAP + y  * IN_HW + xx];
                bufB[l] = feats[cg * NTAP + yp * IN_HW + xx];
            }
            __syncthreads();
            if (x < IN_HW) {
#pragma unroll 8
                for (int ch = 0; ch < 32; ch++) {
                    const float a = bufA[ch * 120 + x];
                    const float b = bufA[ch * 120 + xp];
                    const float c = bufB[ch * 120 + x];
                    const float d = bufB[ch * 120 + xp];
                    s  = fmaf(a, a, s);
                    h  = fmaf(a, b, h);
                    vv = fmaf(a, c, vv);
                    dd = fmaf(a, d, dd);
                    ad = fmaf(b, c, ad);
                }
            }
        }
        if (x < IN_HW) {
            float* o = &g_gram[(y * IN_HW + x) * 8];
            o[0] = s; o[1] = h; o[2] = vv; o[3] = dd; o[4] = ad;
        }
        if (blockIdx.x == 0) {
            if (tid < CPAD) { g_den[tid] = 0.f; g_cnt[tid] = 0.f; }
            if (tid < NC) {
                int isz = 1;
#pragma unroll
                for (int k = 0; k < 16; k++) {
                    float4 v = ((const float4*)memory)[tid * 16 + k];
                    isz &= (v.x == 0.f) & (v.y == 0.f) & (v.z == 0.f) & (v.w == 0.f);
                }
                g_iszero[tid] = isz;
            }
        }
    } else {
        // ---- G table: 24 taps, in-smem transpose from raw feats, (c,q) layout ----
        float* fsm = sbuf;                         // 24 taps x 64 ch
        const int t0 = (blockIdx.x - 120) * 24;
        const int c = tid >> 2, q = tid & 3;
        const bool valid = c < NC;
        float4 mq[4];
        float n2p = 0.f;
#pragma unroll
        for (int j = 0; j < 4; j++) {
            float4 v = valid ? ((const float4*)memory)[c * 16 + q * 4 + j]
                             : make_float4(0.f, 0.f, 0.f, 0.f);
            n2p += v.x * v.x + v.y * v.y + v.z * v.z + v.w * v.w;
            mq[j] = v;
        }
        n2p += __shfl_xor_sync(0xffffffffu, n2p, 1);
        n2p += __shfl_xor_sync(0xffffffffu, n2p, 2);
        const float inv = 1.0f / fmaxf(sqrtf(n2p), EPSV);
#pragma unroll
        for (int j = 0; j < 4; j++) {
            mq[j].x *= inv; mq[j].y *= inv; mq[j].z *= inv; mq[j].w *= inv;
        }
        // transpose-load: fsm[tt*64 + ch] = feats[ch][t0+tt]
#pragma unroll
        for (int k = 0; k < 3; k++) {
            const int l = k * 512 + tid;           // < 1536
            const int ch = l / 24, tt = l - ch * 24;
            fsm[tt * CH + ch] = feats[ch * NTAP + t0 + tt];
        }
        __syncthreads();
#pragma unroll 4
        for (int tt = 0; tt < 24; tt++) {
            const float4* fr = (const float4*)(fsm + tt * CH + q * 16);
            float a0 = 0.f, a1 = 0.f, a2 = 0.f, a3 = 0.f;
#pragma unroll
            for (int j = 0; j < 4; j++) {
                float4 f = fr[j];
                a0 = fmaf(f.x, mq[j].x, a0);
                a1 = fmaf(f.y, mq[j].y, a1);
                a2 = fmaf(f.z, mq[j].z, a2);
                a3 = fmaf(f.w, mq[j].w, a3);
            }
            float d = (a0 + a1) + (a2 + a3);
            d += __shfl_xor_sync(0xffffffffu, d, 1);
            d += __shfl_xor_sync(0xffffffffu, d, 2);
            if (q == 0 && valid) g_G[(t0 + tt) * CPAD + c] = d;
        }
    }
}

// ---------------- per-pixel geometry helper ----------------
struct Geo { int t00, t01, t10, t11; float w00, w01, w10, w11; };
__device__ __forceinline__ Geo pix_geo(int i) {
    const int oy = i / OUT_HW, ox = i - oy * OUT_HW;
    const float fy = 0.25f * (float)oy - 0.375f;
    const float fx = 0.25f * (float)ox - 0.375f;
    const int by = (int)floorf(fy), bx = (int)floorf(fx);
    int y0, x0; float u, v;
    if (by < 0)               { y0 = 0;         u = 0.f; }
    else if (by >= IN_HW - 1) { y0 = IN_HW - 1; u = 0.f; }
    else                      { y0 = by;        u = fy - (float)by; }
    if (bx < 0)               { x0 = 0;         v = 0.f; }
    else if (bx >= IN_HW - 1) { x0 = IN_HW - 1; v = 0.f; }
    else                      { x0 = bx;        v = fx - (float)bx; }
    const int yp = min(y0 + 1, IN_HW - 1), xp = min(x0 + 1, IN_HW - 1);
    const float wu0 = 1.f - u, wv0 = 1.f - v;
    Geo g;
    g.w00 = wu0 * wv0; g.w01 = wu0 * v; g.w10 = u * wv0; g.w11 = u * v;
    g.t00 = y0 * IN_HW + x0; g.t01 = y0 * IN_HW + xp;
    g.t10 = yp * IN_HW + x0; g.t11 = yp * IN_HW + xp;
    return g;
}

__device__ __forceinline__ float pix_sim(const Geo& g, int c) {
    const float dot = g.w00 * g_G[g.t00 * CPAD + c] + g.w01 * g_G[g.t01 * CPAD + c]
                    + g.w10 * g_G[g.t10 * CPAD + c] + g.w11 * g_G[g.t11 * CPAD + c];
    const float4 q00 = *(const float4*)&g_gram[g.t00 * 8];
    const float ad00 = g_gram[g.t00 * 8 + 4];
    const float4 q01 = *(const float4*)&g_gram[g.t01 * 8];
    const float4 q10 = *(const float4*)&g_gram[g.t10 * 8];
    const float S11  = g_gram[g.t11 * 8];
    float n2 = g.w00 * g.w00 * q00.x + g.w01 * g.w01 * q01.x
             + g.w10 * g.w10 * q10.x + g.w11 * g.w11 * S11
             + 2.f * (g.w00 * g.w01 * q00.y + g.w10 * g.w11 * q10.y
                    + g.w00 * g.w10 * q00.z + g.w01 * g.w11 * q01.z
                    + g.w00 * g.w11 * q00.w + g.w01 * g.w10 * ad00);
    n2 = fmaxf(n2, 0.f);
    return 1.f - dot / fmaxf(sqrtf(n2), EPSV);
}

// =============== K2: per-pixel weights + coefficient scatter (2 px/thread) ====
__global__ __launch_bounds__(512) void k_phaseA(const int* __restrict__ seg) {
    __shared__ float s_den[CPAD], s_cnt[CPAD];
    __shared__ int   s_isz[CPAD];
    const int tid = threadIdx.x;
    if (tid < CPAD) {
        s_den[tid] = 0.f; s_cnt[tid] = 0.f;
        s_isz[tid] = (tid < NC) ? g_iszero[tid] : 0;
    }
    __syncthreads();

    const int iA = blockIdx.x * 512 + tid;        // grid 225: iA < 115200
    const int iB = iA + NPIX / 2;
    const int cA = seg[iA];
    const int cB = seg[iB];
    const Geo ga = pix_geo(iA);
    const Geo gb = pix_geo(iB);

    const float sA = pix_sim(ga, cA);
    const float sB = pix_sim(gb, cB);

    const float cmA = s_isz[cA] ? 1.0f : sA;
    const float cmB = s_isz[cB] ? 1.0f : sB;

    atomicAdd(&g_C[ga.t00 * CPAD + cA], cmA * ga.w00);
    atomicAdd(&g_C[ga.t01 * CPAD + cA], cmA * ga.w01);
    atomicAdd(&g_C[ga.t10 * CPAD + cA], cmA * ga.w10);
    atomicAdd(&g_C[ga.t11 * CPAD + cA], cmA * ga.w11);
    atomicAdd(&g_C[gb.t00 * CPAD + cB], cmB * gb.w00);
    atomicAdd(&g_C[gb.t01 * CPAD + cB], cmB * gb.w01);
    atomicAdd(&g_C[gb.t10 * CPAD + cB], cmB * gb.w10);
    atomicAdd(&g_C[gb.t11 * CPAD + cB], cmB * gb.w11);
    atomicAdd(&s_den[cA], cmA);
    atomicAdd(&s_cnt[cA], 1.0f);
    atomicAdd(&s_den[cB], cmB);
    atomicAdd(&s_cnt[cB], 1.0f);

    __syncthreads();
    if (tid < NC) {
        atomicAdd(&g_den[tid], s_den[tid]);
        atomicAdd(&g_cnt[tid], s_cnt[tid]);
    }
}

// =============== K3: output GEMM partials (in-smem transpose, no atomics) =====
// thread (c = tid>>1, h = tid&1); acc[j] covers channels 8j+4h .. 8j+4h+3
__global__ __launch_bounds__(256) void k_out(const float* __restrict__ feats) {
    __shared__ __align__(16) float fsm[24 * CH];     // 6 KB
    __shared__ __align__(16) float csm[24 * CPAD];   // 12 KB
    const int tid = threadIdx.x;
    const int c = tid >> 1, h = tid & 1;
    const int t0 = blockIdx.x * 24;                  // 600 * 24 = 14400

    // transpose-load feats tile: fsm[tt*64 + ch] = feats[ch][t0+tt]
#pragma unroll
    for (int k = 0; k < 6; k++) {
        const int l = k * 256 + tid;                 // < 1536
        const int ch = l / 24, tt = l - ch * 24;
        fsm[tt * CH + ch] = feats[ch * NTAP + t0 + tt];
    }
#pragma unroll
    for (int k = 0; k < 3; k++)
        ((float4*)csm)[tid + k * 256] = ((const float4*)(g_C + t0 * CPAD))[tid + k * 256];
    __syncthreads();

    float4 acc[8];
#pragma unroll
    for (int j = 0; j < 8; j++) acc[j] = make_float4(0.f, 0.f, 0.f, 0.f);

#pragma unroll 4
    for (int tt = 0; tt < 24; tt++) {
        const float coef = csm[tt * CPAD + c];
        const float4* fr = (const float4*)fsm + tt * 16 + h;
#pragma unroll
        for (int j = 0; j < 8; j++) {
            const float4 f = fr[2 * j];
            acc[j].x = fmaf(coef, f.x, acc[j].x);
            acc[j].y = fmaf(coef, f.y, acc[j].y);
            acc[j].z = fmaf(coef, f.z, acc[j].z);
            acc[j].w = fmaf(coef, f.w, acc[j].w);
        }
    }
    // coalesced partial store: g_part4[(b*8+j)*256 + tid]
#pragma unroll
    for (int j = 0; j < 8; j++)
        g_part4[(blockIdx.x * 8 + j) * 256 + tid] = acc[j];
}

// =============== K4: reduce partials + final blend (16-way split, 1024 thr) ===
__global__ __launch_bounds__(1024) void k_blend(const float* __restrict__ memory,
                                                float* __restrict__ out) {
    __shared__ float red[1024];
    const int c  = blockIdx.x;                 // 0..123
    const int ch = threadIdx.x & 63;
    const int w  = threadIdx.x >> 6;           // 0..15 split over partial blocks
    const int j  = ch >> 3, h = (ch >> 2) & 1, k = ch & 3;
    const float* P = (const float*)g_part4;
    const int base = j * 1024 + (2 * c + h) * 4 + k;   // + b*8192

    float sum = 0.f;
#pragma unroll 8
    for (int b = w; b < NOUTB; b += 16)
        sum += P[base + b * 8192];
    red[threadIdx.x] = sum;
    __syncthreads();

    if (w == 0) {
        float accv = 0.f;
#pragma unroll
        for (int s = 0; s < 16; s++) accv += red[ch + 64 * s];
        const float mem = memory[c * CH + ch];
        const float cnt = g_cnt[c];
        float o;
        if (cnt < 0.5f) {
            o = mem;                                     // class absent
        } else if (g_iszero[c]) {
            o = accv / fmaxf(g_den[c], 1.0f);            // class mean (den==cnt)
        } else {
            const float dv = g_den[c];
            const float denom = (dv != 0.0f) ? dv : 1.0f;
            o = 0.9f * mem + 0.1f * (accv / denom);      // momentum update
        }
        out[c * CH + ch] = o;
    }
}

// ---------------- launch ----------------
extern "C" void kernel_launch(void* const* d_in, const int* in_sizes, int n_in,
                              void* d_out, int out_size) {
    const float* feats  = (const float*)d_in[0];   // (1,64,120,120)
    const float* memory = (const float*)d_in[1];   // (124,1,64)
    const int*   seg    = (const int*)d_in[2];     // (1,480,480)
    float* out = (float*)d_out;                    // (124,1,64)

    k_gramG<<<K1B, 512>>>(feats, memory);
    k_phaseA<<<225, 512>>>(seg);
    k_out<<<NOUTB, 256>>>(feats);
    k_blend<<<NC, 1024>>>(memory, out);
}